// round 1
// baseline (speedup 1.0000x reference)
#include <cuda_runtime.h>
#include <math.h>

#define DIM      256
#define NSEG     32768
#define CHUNK    128
#define NTHREADS 256

// Allocation-free scratch: segment start offsets (batch is sorted).
__device__ int g_seg_start[NSEG + 1];

// lower_bound(batch, b) for b in [0, NSEG]; batch is sorted int32 of length V.
__global__ void seg_bounds_kernel(const int* __restrict__ batch, int V) {
    int b = blockIdx.x * blockDim.x + threadIdx.x;
    if (b > NSEG) return;
    int lo = 0, hi = V;
    while (lo < hi) {
        int mid = (lo + hi) >> 1;
        if (batch[mid] < b) lo = mid + 1; else hi = mid;
    }
    g_seg_start[b] = lo;
}

// One block per segment. 256 threads.
// Phase 1: warp-per-row dot(H[row], Ww) + bias -> scores in smem.
// Phase 2: block max / exp / sum (online softmax across chunks).
// Phase 3: thread-per-column weighted accumulation (rows re-read hit L1/L2).
__global__ __launch_bounds__(NTHREADS)
void agg_kernel(const float* __restrict__ H, const float* __restrict__ Ww,
                const float* __restrict__ Wb, float* __restrict__ out) {
    const int b    = blockIdx.x;
    const int t    = threadIdx.x;
    const int warp = t >> 5;
    const int lane = t & 31;

    const int start = g_seg_start[b];
    const int end   = g_seg_start[b + 1];

    __shared__ float sWw[DIM];
    __shared__ float sc[CHUNK];
    __shared__ float red[NTHREADS / 32];
    __shared__ float s_bcast;

    sWw[t] = Ww[t];
    const float bias = Wb[0];
    __syncthreads();

    float acc  = 0.0f;        // running sum of e_i * H[i][t] (column t)
    float m    = -INFINITY;   // running max
    float ssum = 0.0f;        // running sum of exponentials

    const float4* sWw4 = (const float4*)sWw;
    const float4  wa   = sWw4[lane];
    const float4  wc   = sWw4[lane + 32];

    for (int pos = start; pos < end; pos += CHUNK) {
        const int n = min(CHUNK, end - pos);

        // ---- Phase 1: scores (warp per row, 2x coalesced float4 loads) ----
        for (int r = warp; r < CHUNK; r += NTHREADS / 32) {
            float v = -INFINITY;
            if (r < n) {
                const float4* hp = (const float4*)(H + (long)(pos + r) * DIM);
                float4 a = hp[lane];
                float4 c = hp[lane + 32];
                float d = a.x * wa.x + a.y * wa.y + a.z * wa.z + a.w * wa.w
                        + c.x * wc.x + c.y * wc.y + c.z * wc.z + c.w * wc.w;
                #pragma unroll
                for (int o = 16; o > 0; o >>= 1)
                    d += __shfl_down_sync(0xFFFFFFFFu, d, o);
                v = d + bias;
            }
            if (lane == 0) sc[r] = v;
        }
        __syncthreads();

        // ---- Phase 2a: chunk max ----
        float cm = (t < CHUNK) ? sc[t] : -INFINITY;
        #pragma unroll
        for (int o = 16; o > 0; o >>= 1)
            cm = fmaxf(cm, __shfl_xor_sync(0xFFFFFFFFu, cm, o));
        if (lane == 0) red[warp] = cm;
        __syncthreads();
        if (t == 0) {
            float x = red[0];
            #pragma unroll
            for (int i = 1; i < NTHREADS / 32; ++i) x = fmaxf(x, red[i]);
            s_bcast = x;
        }
        __syncthreads();

        const float m_new = fmaxf(m, s_bcast);
        const float scale = __expf(m - m_new);   // 0 when m == -inf
        ssum *= scale;
        acc  *= scale;
        m     = m_new;
        __syncthreads();  // everyone has read s_bcast / sc before rewrite

        // ---- Phase 2b: exponentials + their sum ----
        if (t < CHUNK) sc[t] = (t < n) ? __expf(sc[t] - m_new) : 0.0f;
        float e = (t < CHUNK) ? sc[t] : 0.0f;    // own slot, no hazard
        #pragma unroll
        for (int o = 16; o > 0; o >>= 1)
            e += __shfl_xor_sync(0xFFFFFFFFu, e, o);
        if (lane == 0) red[warp] = e;
        __syncthreads();
        if (t == 0) {
            float x = 0.0f;
            #pragma unroll
            for (int i = 0; i < NTHREADS / 32; ++i) x += red[i];
            s_bcast = x;
        }
        __syncthreads();
        ssum += s_bcast;

        // ---- Phase 3: weighted accumulation, thread t owns column t ----
        const float* hcol = H + (long)pos * DIM + t;
        int r = 0;
        #pragma unroll 4
        for (; r + 4 <= n; r += 4) {
            float e0 = sc[r + 0], e1 = sc[r + 1], e2 = sc[r + 2], e3 = sc[r + 3];
            float h0 = hcol[(long)(r + 0) * DIM];
            float h1 = hcol[(long)(r + 1) * DIM];
            float h2 = hcol[(long)(r + 2) * DIM];
            float h3 = hcol[(long)(r + 3) * DIM];
            acc = fmaf(e0, h0, acc);
            acc = fmaf(e1, h1, acc);
            acc = fmaf(e2, h2, acc);
            acc = fmaf(e3, h3, acc);
        }
        for (; r < n; ++r)
            acc = fmaf(sc[r], hcol[(long)r * DIM], acc);

        __syncthreads();  // sc/red reused next chunk
    }

    out[(long)b * DIM + t] = (ssum > 0.0f) ? (acc / ssum) : 0.0f;
}

extern "C" void kernel_launch(void* const* d_in, const int* in_sizes, int n_in,
                              void* d_out, int out_size) {
    const float* H     = (const float*)d_in[0];
    const int*   batch = (const int*)d_in[1];
    const float* Ww    = (const float*)d_in[2];
    const float* Wb    = (const float*)d_in[3];
    float*       out   = (float*)d_out;
    const int V = in_sizes[1];  // batch[] element count

    seg_bounds_kernel<<<(NSEG + 1 + 255) / 256, 256>>>(batch, V);
    agg_kernel<<<NSEG, NTHREADS>>>(H, Ww, Wb, out);
}

// round 2
// speedup vs baseline: 1.2792x; 1.2792x over previous
#include <cuda_runtime.h>
#include <math.h>

#define DIM      256
#define NSEG     32768
#define RPI      4          // rows per iteration (8 independent LDG.128/thread)
#define WPB      8          // warps per block

// Allocation-free scratch: segment start offsets (batch is sorted).
__device__ int g_seg_start[NSEG + 1];

// lower_bound(batch, b) for b in [0, NSEG]; batch is sorted int32 of length V.
__global__ void seg_bounds_kernel(const int* __restrict__ batch, int V) {
    int b = blockIdx.x * blockDim.x + threadIdx.x;
    if (b > NSEG) return;
    int lo = 0, hi = V;
    while (lo < hi) {
        int mid = (lo + hi) >> 1;
        if (batch[mid] < b) lo = mid + 1; else hi = mid;
    }
    g_seg_start[b] = lo;
}

// One WARP per segment. Single pass over H with online softmax:
// row data used for the score is still in registers for the weighted
// accumulate -> H read exactly once, no smem, no __syncthreads.
// Thread owns columns [4*lane..4*lane+3] and [128+4*lane..128+4*lane+3].
__global__ __launch_bounds__(32 * WPB)
void agg_warp_kernel(const float4* __restrict__ H4,
                     const float4* __restrict__ Ww4,
                     const float*  __restrict__ Wb,
                     float4*       __restrict__ out4) {
    const int lane = threadIdx.x & 31;
    const int b    = blockIdx.x * WPB + (threadIdx.x >> 5);

    const int start = g_seg_start[b];
    const int end   = g_seg_start[b + 1];

    const float4 w0   = Ww4[lane];
    const float4 w1   = Ww4[lane + 32];
    const float  bias = Wb[0];

    float4 acc0 = make_float4(0.f, 0.f, 0.f, 0.f);
    float4 acc1 = make_float4(0.f, 0.f, 0.f, 0.f);
    float  m    = -INFINITY;
    float  ssum = 0.0f;

    for (int pos = start; pos < end; pos += RPI) {
        const int nr = end - pos;   // >=1; rows beyond nr are padded

        // ---- batched loads: up to 8 independent LDG.128 in flight ----
        float4 h0[RPI], h1[RPI];
        #pragma unroll
        for (int i = 0; i < RPI; ++i) {
            if (i < nr) {
                const float4* row = H4 + (long)(pos + i) * (DIM / 4);
                h0[i] = row[lane];
                h1[i] = row[lane + 32];
            } else {
                h0[i] = make_float4(0.f, 0.f, 0.f, 0.f);
                h1[i] = make_float4(0.f, 0.f, 0.f, 0.f);
            }
        }

        // ---- partial dots (8 fma each), then 4 interleaved shfl reductions ----
        float s[RPI];
        #pragma unroll
        for (int i = 0; i < RPI; ++i) {
            float d = h0[i].x * w0.x;
            d = fmaf(h0[i].y, w0.y, d);
            d = fmaf(h0[i].z, w0.z, d);
            d = fmaf(h0[i].w, w0.w, d);
            d = fmaf(h1[i].x, w1.x, d);
            d = fmaf(h1[i].y, w1.y, d);
            d = fmaf(h1[i].z, w1.z, d);
            d = fmaf(h1[i].w, w1.w, d);
            s[i] = d;
        }
        #pragma unroll
        for (int o = 16; o > 0; o >>= 1) {
            #pragma unroll
            for (int i = 0; i < RPI; ++i)
                s[i] += __shfl_xor_sync(0xFFFFFFFFu, s[i], o);
        }

        // ---- online softmax update ----
        float cm = -INFINITY;
        #pragma unroll
        for (int i = 0; i < RPI; ++i) {
            s[i] = (i < nr) ? (s[i] + bias) : -INFINITY;
            cm = fmaxf(cm, s[i]);
        }
        const float m_new = fmaxf(m, cm);
        const float scale = __expf(m - m_new);   // 0 on first iteration
        ssum *= scale;
        acc0.x *= scale; acc0.y *= scale; acc0.z *= scale; acc0.w *= scale;
        acc1.x *= scale; acc1.y *= scale; acc1.z *= scale; acc1.w *= scale;
        m = m_new;

        #pragma unroll
        for (int i = 0; i < RPI; ++i) {
            const float e = __expf(s[i] - m_new);   // 0 for padded rows
            ssum += e;
            acc0.x = fmaf(e, h0[i].x, acc0.x);
            acc0.y = fmaf(e, h0[i].y, acc0.y);
            acc0.z = fmaf(e, h0[i].z, acc0.z);
            acc0.w = fmaf(e, h0[i].w, acc0.w);
            acc1.x = fmaf(e, h1[i].x, acc1.x);
            acc1.y = fmaf(e, h1[i].y, acc1.y);
            acc1.z = fmaf(e, h1[i].z, acc1.z);
            acc1.w = fmaf(e, h1[i].w, acc1.w);
        }
    }

    const float inv = (ssum > 0.0f) ? (1.0f / ssum) : 0.0f;  // empty -> zeros
    float4 o0 = make_float4(acc0.x * inv, acc0.y * inv, acc0.z * inv, acc0.w * inv);
    float4 o1 = make_float4(acc1.x * inv, acc1.y * inv, acc1.z * inv, acc1.w * inv);
    out4[(long)b * (DIM / 4) + lane]      = o0;
    out4[(long)b * (DIM / 4) + 32 + lane] = o1;
}

extern "C" void kernel_launch(void* const* d_in, const int* in_sizes, int n_in,
                              void* d_out, int out_size) {
    const float* H     = (const float*)d_in[0];
    const int*   batch = (const int*)d_in[1];
    const float* Ww    = (const float*)d_in[2];
    const float* Wb    = (const float*)d_in[3];
    float*       out   = (float*)d_out;
    const int V = in_sizes[1];  // batch[] element count

    seg_bounds_kernel<<<(NSEG + 1 + 255) / 256, 256>>>(batch, V);
    agg_warp_kernel<<<NSEG / WPB, 32 * WPB>>>(
        (const float4*)H, (const float4*)Ww, Wb, (float4*)out);
}

// round 3
// speedup vs baseline: 1.4180x; 1.1085x over previous
#include <cuda_runtime.h>
#include <math.h>

#define DIM      256
#define NSEG     32768
#define RPI      4          // rows per iteration (8 independent LDG.128/thread)
#define WPB      4          // warps per block (small -> fast resource retirement)

// Allocation-free scratch: segment start offsets (batch is sorted).
__device__ int g_seg_start[NSEG + 1];

// Linear boundary scan: batch is sorted, so g_seg_start[b] = first i with
// batch[i] >= b. Thread i claims all b in (batch[i-1], batch[i]].
__global__ void seg_bounds_scan(const int* __restrict__ batch, int V) {
    int i = blockIdx.x * blockDim.x + threadIdx.x;
    if (i >= V) return;
    int cur  = batch[i];
    int prev = (i == 0) ? -1 : batch[i - 1];
    for (int b = prev + 1; b <= cur; ++b) g_seg_start[b] = i;
    if (i == V - 1) {
        for (int b = cur + 1; b <= NSEG; ++b) g_seg_start[b] = V;
    }
}

// One WARP per segment, single pass over H with online softmax.
// Row data used for the score is still in registers for the weighted
// accumulate -> H read exactly once. Streaming loads (evict-first):
// no reuse exists, keep L2 clean.
__global__ __launch_bounds__(32 * WPB)
void agg_warp_kernel(const float4* __restrict__ H4,
                     const float4* __restrict__ Ww4,
                     const float*  __restrict__ Wb,
                     float4*       __restrict__ out4) {
    const int lane = threadIdx.x & 31;
    const int b    = blockIdx.x * WPB + (threadIdx.x >> 5);

    const int start = g_seg_start[b];
    const int end   = g_seg_start[b + 1];

    const float4 w0   = Ww4[lane];
    const float4 w1   = Ww4[lane + 32];
    const float  bias = Wb[0];

    float4 acc0 = make_float4(0.f, 0.f, 0.f, 0.f);
    float4 acc1 = make_float4(0.f, 0.f, 0.f, 0.f);
    float  m    = -INFINITY;
    float  ssum = 0.0f;

    for (int pos = start; pos < end; pos += RPI) {
        const int nr = end - pos;   // rows beyond nr are padded

        // ---- batched loads: up to 8 independent LDG.128.CS in flight ----
        float4 h0[RPI], h1[RPI];
        #pragma unroll
        for (int i = 0; i < RPI; ++i) {
            if (i < nr) {
                const float4* row = H4 + (long)(pos + i) * (DIM / 4);
                h0[i] = __ldcs(row + lane);
                h1[i] = __ldcs(row + lane + 32);
            } else {
                h0[i] = make_float4(0.f, 0.f, 0.f, 0.f);
                h1[i] = make_float4(0.f, 0.f, 0.f, 0.f);
            }
        }

        // ---- partial dots, then 4 interleaved shfl reductions ----
        float s[RPI];
        #pragma unroll
        for (int i = 0; i < RPI; ++i) {
            float d = h0[i].x * w0.x;
            d = fmaf(h0[i].y, w0.y, d);
            d = fmaf(h0[i].z, w0.z, d);
            d = fmaf(h0[i].w, w0.w, d);
            d = fmaf(h1[i].x, w1.x, d);
            d = fmaf(h1[i].y, w1.y, d);
            d = fmaf(h1[i].z, w1.z, d);
            d = fmaf(h1[i].w, w1.w, d);
            s[i] = d;
        }
        #pragma unroll
        for (int o = 16; o > 0; o >>= 1) {
            #pragma unroll
            for (int i = 0; i < RPI; ++i)
                s[i] += __shfl_xor_sync(0xFFFFFFFFu, s[i], o);
        }

        // ---- online softmax update ----
        float cm = -INFINITY;
        #pragma unroll
        for (int i = 0; i < RPI; ++i) {
            s[i] = (i < nr) ? (s[i] + bias) : -INFINITY;
            cm = fmaxf(cm, s[i]);
        }
        const float m_new = fmaxf(m, cm);
        const float scale = __expf(m - m_new);   // 0 on first iteration
        ssum *= scale;
        acc0.x *= scale; acc0.y *= scale; acc0.z *= scale; acc0.w *= scale;
        acc1.x *= scale; acc1.y *= scale; acc1.z *= scale; acc1.w *= scale;
        m = m_new;

        #pragma unroll
        for (int i = 0; i < RPI; ++i) {
            const float e = __expf(s[i] - m_new);   // 0 for padded rows
            ssum += e;
            acc0.x = fmaf(e, h0[i].x, acc0.x);
            acc0.y = fmaf(e, h0[i].y, acc0.y);
            acc0.z = fmaf(e, h0[i].z, acc0.z);
            acc0.w = fmaf(e, h0[i].w, acc0.w);
            acc1.x = fmaf(e, h1[i].x, acc1.x);
            acc1.y = fmaf(e, h1[i].y, acc1.y);
            acc1.z = fmaf(e, h1[i].z, acc1.z);
            acc1.w = fmaf(e, h1[i].w, acc1.w);
        }
    }

    const float inv = (ssum > 0.0f) ? (1.0f / ssum) : 0.0f;  // empty -> zeros
    float4 o0 = make_float4(acc0.x * inv, acc0.y * inv, acc0.z * inv, acc0.w * inv);
    float4 o1 = make_float4(acc1.x * inv, acc1.y * inv, acc1.z * inv, acc1.w * inv);
    out4[(long)b * (DIM / 4) + lane]      = o0;
    out4[(long)b * (DIM / 4) + 32 + lane] = o1;
}

extern "C" void kernel_launch(void* const* d_in, const int* in_sizes, int n_in,
                              void* d_out, int out_size) {
    const float* H     = (const float*)d_in[0];
    const int*   batch = (const int*)d_in[1];
    const float* Ww    = (const float*)d_in[2];
    const float* Wb    = (const float*)d_in[3];
    float*       out   = (float*)d_out;
    const int V = in_sizes[1];  // batch[] element count

    seg_bounds_scan<<<(V + 255) / 256, 256>>>(batch, V);
    agg_warp_kernel<<<NSEG / WPB, 32 * WPB>>>(
        (const float4*)H, (const float4*)Ww, Wb, (float4*)out);
}